// round 2
// baseline (speedup 1.0000x reference)
#include <cuda_runtime.h>
#include <cstdint>

#define H 256

// max sizes (fixed problem shapes)
#define MAXV 100000
#define MAXE 150000
#define MAXL 80000
#define MAXF 60000

// scratch
__device__ float    g_v[(size_t)MAXV * H];   // vertex embed; later reused as loop-conv output
__device__ float    g_e[(size_t)MAXE * H];   // edge embed
__device__ float    g_eo[(size_t)MAXE * H];  // edge conv output
__device__ float    g_l[(size_t)MAXL * H];   // loop embed
__device__ float    g_f[(size_t)MAXF * H];   // face embed
__device__ unsigned g_min[(size_t)MAXE * H]; // segment-min (encoded), then (x - min) as float

// ---------- helpers ----------
__device__ __forceinline__ float leaky(float a) { return a >= 0.f ? a : 0.01f * a; }

// monotone float<->uint encoding so unsigned atomicMin == float min
__device__ __forceinline__ unsigned enc(float x) {
    unsigned u = __float_as_uint(x);
    return u ^ ((unsigned)((int)u >> 31) | 0x80000000u);
}
__device__ __forceinline__ float dec(unsigned k) {
    unsigned u = (k & 0x80000000u) ? (k ^ 0x80000000u) : ~k;
    return __uint_as_float(u);
}

// ---------- embedding: out = leaky([s0|s1|s2] @ W + b), 8 rows per block ----------
__global__ void embed_kernel(const float* __restrict__ s0, int w0,
                             const float* __restrict__ s1, int w1,
                             const float* __restrict__ s2, int w2,
                             const float* __restrict__ W, const float* __restrict__ bias,
                             float* __restrict__ out, int n) {
    const int R = 8;
    int row0 = blockIdx.x * R;
    int t = threadIdx.x;               // 256 threads, one out-dim each
    int IN = w0 + w1 + w2;
    __shared__ float xs[R][20];

    for (int i = t; i < R * IN; i += 256) {
        int r = i / IN, k = i % IN;
        int row = row0 + r;
        float v = 0.f;
        if (row < n) {
            if (k < w0)             v = s0[(size_t)row * w0 + k];
            else if (k < w0 + w1)   v = s1[(size_t)row * w1 + (k - w0)];
            else                    v = s2[row];   // flipped scalar (w2 == 1)
        }
        xs[r][k] = v;
    }
    __syncthreads();

    float bb = bias[t];
    float acc[R];
#pragma unroll
    for (int r = 0; r < R; r++) acc[r] = bb;
    for (int k = 0; k < IN; k++) {
        float w = W[(size_t)k * H + t];
#pragma unroll
        for (int r = 0; r < R; r++) acc[r] += xs[r][k] * w;
    }
#pragma unroll
    for (int r = 0; r < R; r++) {
        int row = row0 + r;
        if (row < n) out[(size_t)row * H + t] = leaky(acc[r]);
    }
}

// ---------- segment-min: one warp per pair, atomicMin over encoded floats ----------
__global__ void segmin_kernel(const int* __restrict__ dstIdx,
                              const int* __restrict__ srcIdx,
                              int n_pairs,
                              const float* __restrict__ xsrc,
                              unsigned* __restrict__ out) {
    int warp = (blockIdx.x * blockDim.x + threadIdx.x) >> 5;
    int lane = threadIdx.x & 31;
    if (warp >= n_pairs) return;
    int dst = dstIdx[warp];
    int src = srcIdx[warp];
    const float4* s = reinterpret_cast<const float4*>(xsrc + (size_t)src * H);
    unsigned* d = out + (size_t)dst * H;
#pragma unroll
    for (int j = 0; j < 2; j++) {
        int c = lane + j * 32;        // float4 index 0..63
        float4 v = s[c];
        atomicMin(&d[c * 4 + 0], enc(v.x));
        atomicMin(&d[c * 4 + 1], enc(v.y));
        atomicMin(&d[c * 4 + 2], enc(v.z));
        atomicMin(&d[c * 4 + 3], enc(v.w));
    }
}

// ---------- finish: m <- x_dst - decode(min)  (this is the "maxes" half of the concat) ----------
__global__ void finish_min_kernel(const float* __restrict__ x, unsigned* __restrict__ m, size_t nElem) {
    size_t i = (size_t)blockIdx.x * blockDim.x + threadIdx.x;
    size_t stride = (size_t)gridDim.x * blockDim.x;
    float* mf = reinterpret_cast<float*>(m);
    for (; i < nElem; i += stride)
        mf[i] = x[i] - dec(m[i]);
}

// ---------- conv GEMM: out = x + leaky([x | mh] @ W + b), K=512, N=256 ----------
__global__ void conv_gemm_kernel(const float* __restrict__ x, const float* __restrict__ mh,
                                 const float* __restrict__ W, const float* __restrict__ bias,
                                 float* __restrict__ out, int M) {
    __shared__ float As[16][68];
    __shared__ float Bs[16][68];
    int bm = blockIdx.x * 64;
    int bn = blockIdx.y * 64;
    int tid = threadIdx.x;             // 256
    int tx = tid & 15, ty = tid >> 4;

    float acc[4][4];
#pragma unroll
    for (int i = 0; i < 4; i++)
#pragma unroll
        for (int j = 0; j < 4; j++) acc[i][j] = 0.f;

    for (int k0 = 0; k0 < 512; k0 += 16) {
        // A tile 64x16 (assembled from x for k<256, mh for k>=256)
        {
            const float* Ab = (k0 < 256) ? x : mh;
            int kk = k0 & 255;
            int r = tid >> 2;
            int c4 = (tid & 3) * 4;
            int row = bm + r;
            float4 v = make_float4(0.f, 0.f, 0.f, 0.f);
            if (row < M) v = *reinterpret_cast<const float4*>(Ab + (size_t)row * H + kk + c4);
            As[c4 + 0][r] = v.x; As[c4 + 1][r] = v.y;
            As[c4 + 2][r] = v.z; As[c4 + 3][r] = v.w;
        }
        // B tile 16x64
        {
            int r = tid >> 4;
            int c4 = (tid & 15) * 4;
            float4 v = *reinterpret_cast<const float4*>(W + (size_t)(k0 + r) * H + bn + c4);
            *reinterpret_cast<float4*>(&Bs[r][c4]) = v;
        }
        __syncthreads();
#pragma unroll
        for (int k = 0; k < 16; k++) {
            float4 a = *reinterpret_cast<const float4*>(&As[k][ty * 4]);
            float4 b = *reinterpret_cast<const float4*>(&Bs[k][tx * 4]);
            float av[4] = {a.x, a.y, a.z, a.w};
            float bv[4] = {b.x, b.y, b.z, b.w};
#pragma unroll
            for (int i = 0; i < 4; i++)
#pragma unroll
                for (int j = 0; j < 4; j++) acc[i][j] += av[i] * bv[j];
        }
        __syncthreads();
    }

#pragma unroll
    for (int i = 0; i < 4; i++) {
        int row = bm + ty * 4 + i;
        if (row >= M) continue;
#pragma unroll
        for (int j = 0; j < 4; j++) {
            int col = bn + tx * 4 + j;
            float a = leaky(acc[i][j] + bias[col]);
            out[(size_t)row * H + col] = x[(size_t)row * H + col] + a;
        }
    }
}

// ---------- launch ----------
static inline int cdiv(int a, int b) { return (a + b - 1) / b; }

extern "C" void kernel_launch(void* const* d_in, const int* in_sizes, int n_in,
                              void* d_out, int out_size) {
    const float* vp  = (const float*)d_in[0];
    const float* ec  = (const float*)d_in[1];
    const float* ecp = (const float*)d_in[2];
    const float* ecf = (const float*)d_in[3];
    const float* lt  = (const float*)d_in[4];
    const float* fs  = (const float*)d_in[5];
    const float* fsp = (const float*)d_in[6];
    const float* fsf = (const float*)d_in[7];
    const int* ev = (const int*)d_in[8];
    const int* le = (const int*)d_in[9];
    const int* fl = (const int*)d_in[10];
    const float* Wv = (const float*)d_in[11]; const float* bv = (const float*)d_in[12];
    const float* We = (const float*)d_in[13]; const float* be = (const float*)d_in[14];
    const float* Wl = (const float*)d_in[15]; const float* bl = (const float*)d_in[16];
    const float* Wf = (const float*)d_in[17]; const float* bf = (const float*)d_in[18];
    const float* Wve = (const float*)d_in[19]; const float* bve = (const float*)d_in[20];
    const float* Wel = (const float*)d_in[21]; const float* bel = (const float*)d_in[22];
    const float* Wlf = (const float*)d_in[23]; const float* blf = (const float*)d_in[24];

    int NVn = in_sizes[0] / 3;
    int NEn = in_sizes[1] / 8;
    int NLn = in_sizes[4] / 10;
    int NFn = in_sizes[5] / 12;
    int nEV = in_sizes[8] / 2;
    int nLE = in_sizes[9] / 2;
    int nFL = in_sizes[10] / 2;

    float *pv, *pe, *peo, *pl, *pf;
    unsigned* pm;
    cudaGetSymbolAddress((void**)&pv,  g_v);
    cudaGetSymbolAddress((void**)&pe,  g_e);
    cudaGetSymbolAddress((void**)&peo, g_eo);
    cudaGetSymbolAddress((void**)&pl,  g_l);
    cudaGetSymbolAddress((void**)&pf,  g_f);
    cudaGetSymbolAddress((void**)&pm,  g_min);

    // --- embeddings ---
    embed_kernel<<<cdiv(NVn, 8), 256>>>(vp, 3, nullptr, 0, nullptr, 0, Wv, bv, pv, NVn);
    embed_kernel<<<cdiv(NEn, 8), 256>>>(ec, 8, ecp, 6, ecf, 1, We, be, pe, NEn);
    embed_kernel<<<cdiv(NLn, 8), 256>>>(lt, 10, nullptr, 0, nullptr, 0, Wl, bl, pl, NLn);
    embed_kernel<<<cdiv(NFn, 8), 256>>>(fs, 12, fsp, 4, fsf, 1, Wf, bf, pf, NFn);

    // --- conv 1: vertices -> edges ---
    cudaMemsetAsync(pm, 0xFF, (size_t)NEn * H * sizeof(unsigned));
    segmin_kernel<<<cdiv(nEV, 8), 256>>>(ev, ev + nEV, nEV, pv, pm);
    finish_min_kernel<<<2048, 256>>>(pe, pm, (size_t)NEn * H);
    {
        dim3 g(cdiv(NEn, 64), 4);
        conv_gemm_kernel<<<g, 256>>>(pe, (const float*)pm, Wve, bve, peo, NEn);
    }

    // --- conv 2: edges -> loops (output reuses g_v) ---
    cudaMemsetAsync(pm, 0xFF, (size_t)NLn * H * sizeof(unsigned));
    segmin_kernel<<<cdiv(nLE, 8), 256>>>(le, le + nLE, nLE, peo, pm);
    finish_min_kernel<<<2048, 256>>>(pl, pm, (size_t)NLn * H);
    {
        dim3 g(cdiv(NLn, 64), 4);
        conv_gemm_kernel<<<g, 256>>>(pl, (const float*)pm, Wel, bel, pv, NLn);
    }

    // --- conv 3: loops -> faces (output = d_out) ---
    cudaMemsetAsync(pm, 0xFF, (size_t)NFn * H * sizeof(unsigned));
    segmin_kernel<<<cdiv(nFL, 8), 256>>>(fl, fl + nFL, nFL, pv, pm);
    finish_min_kernel<<<2048, 256>>>(pf, pm, (size_t)NFn * H);
    {
        dim3 g(cdiv(NFn, 64), 4);
        conv_gemm_kernel<<<g, 256>>>(pf, (const float*)pm, Wlf, blf, (float*)d_out, NFn);
    }
}

// round 3
// speedup vs baseline: 2.0170x; 2.0170x over previous
#include <cuda_runtime.h>
#include <cstdint>

#define H 256

#define MAXV 100000
#define MAXE 150000
#define MAXL 80000
#define MAXF 60000
#define MAXPAIR 320000

// scratch
__device__ float    g_v[(size_t)MAXV * H];   // vertex embed; later reused as loop-conv output
__device__ float    g_e[(size_t)MAXE * H];   // edge embed
__device__ float    g_eo[(size_t)MAXE * H];  // edge conv output
__device__ float    g_l[(size_t)MAXL * H];   // loop embed
__device__ float    g_f[(size_t)MAXF * H];   // face embed
__device__ float    g_mh[(size_t)MAXE * H];  // (x_dst - segment_min) buffer
__device__ int      g_cnt[MAXE + 1];
__device__ int      g_off[MAXE + 1];
__device__ int      g_cur[MAXE + 1];
__device__ int      g_col[MAXPAIR];

// ---------- helpers ----------
__device__ __forceinline__ float leaky(float a) { return a >= 0.f ? a : 0.01f * a; }

__device__ __forceinline__ unsigned f2tf32(float f) {
    unsigned r;
    asm("cvt.rna.tf32.f32 %0, %1;" : "=r"(r) : "f"(f));
    return r;
}

__device__ __forceinline__ void mma_tf32(float c[4], const unsigned a[4], const unsigned b[2]) {
    asm volatile(
        "mma.sync.aligned.m16n8k8.row.col.f32.tf32.tf32.f32 "
        "{%0,%1,%2,%3},{%4,%5,%6,%7},{%8,%9},{%0,%1,%2,%3};"
        : "+f"(c[0]), "+f"(c[1]), "+f"(c[2]), "+f"(c[3])
        : "r"(a[0]), "r"(a[1]), "r"(a[2]), "r"(a[3]), "r"(b[0]), "r"(b[1]));
}

// ---------- embedding: out = leaky([s0|s1|s2] @ W + b), 8 rows per block ----------
__global__ void embed_kernel(const float* __restrict__ s0, int w0,
                             const float* __restrict__ s1, int w1,
                             const float* __restrict__ s2, int w2,
                             const float* __restrict__ W, const float* __restrict__ bias,
                             float* __restrict__ out, int n) {
    const int R = 8;
    int row0 = blockIdx.x * R;
    int t = threadIdx.x;
    int IN = w0 + w1 + w2;
    __shared__ float xs[R][20];

    for (int i = t; i < R * IN; i += 256) {
        int r = i / IN, k = i % IN;
        int row = row0 + r;
        float v = 0.f;
        if (row < n) {
            if (k < w0)             v = s0[(size_t)row * w0 + k];
            else if (k < w0 + w1)   v = s1[(size_t)row * w1 + (k - w0)];
            else                    v = s2[row];
        }
        xs[r][k] = v;
    }
    __syncthreads();

    float bb = bias[t];
    float acc[R];
#pragma unroll
    for (int r = 0; r < R; r++) acc[r] = bb;
    for (int k = 0; k < IN; k++) {
        float w = W[(size_t)k * H + t];
#pragma unroll
        for (int r = 0; r < R; r++) acc[r] += xs[r][k] * w;
    }
#pragma unroll
    for (int r = 0; r < R; r++) {
        int row = row0 + r;
        if (row < n) out[(size_t)row * H + t] = leaky(acc[r]);
    }
}

// ---------- CSR build ----------
__global__ void count_kernel(const int* __restrict__ dst, int n_pairs, int* __restrict__ cnt) {
    int i = blockIdx.x * blockDim.x + threadIdx.x;
    if (i < n_pairs) atomicAdd(&cnt[dst[i]], 1);
}

// single-block scan: off = exclusive scan of cnt, cur = copy, off[n] = total
__global__ void scan_kernel(const int* __restrict__ cnt, int n,
                            int* __restrict__ off, int* __restrict__ cur) {
    __shared__ int wsum[32];
    __shared__ int s_carry;
    int tid = threadIdx.x;
    int lane = tid & 31, wid = tid >> 5;
    if (tid == 0) s_carry = 0;
    __syncthreads();
    for (int base = 0; base < n; base += 1024) {
        int i = base + tid;
        int v = (i < n) ? cnt[i] : 0;
        int x = v;
#pragma unroll
        for (int d = 1; d < 32; d <<= 1) {
            int y = __shfl_up_sync(~0u, x, d);
            if (lane >= d) x += y;
        }
        if (lane == 31) wsum[wid] = x;
        __syncthreads();
        if (wid == 0) {
            int w = wsum[lane];
#pragma unroll
            for (int d = 1; d < 32; d <<= 1) {
                int y = __shfl_up_sync(~0u, w, d);
                if (lane >= d) w += y;
            }
            wsum[lane] = w;
        }
        __syncthreads();
        int incl = x + (wid > 0 ? wsum[wid - 1] : 0) + s_carry;
        int excl = incl - v;
        if (i < n) { off[i] = excl; cur[i] = excl; }
        __syncthreads();
        if (tid == 1023) s_carry = incl;
        __syncthreads();
    }
    if (tid == 0) off[n] = s_carry;
}

__global__ void fill_kernel(const int* __restrict__ dst, const int* __restrict__ src,
                            int n_pairs, int* __restrict__ cur, int* __restrict__ col) {
    int i = blockIdx.x * blockDim.x + threadIdx.x;
    if (i < n_pairs) {
        int pos = atomicAdd(&cur[dst[i]], 1);
        col[pos] = src[i];
    }
}

// ---------- fused segment-min + (x_dst - min): one warp per segment ----------
__global__ void segmin_csr_kernel(const int* __restrict__ off, const int* __restrict__ col,
                                  int n_dst,
                                  const float* __restrict__ xsrc,
                                  const float* __restrict__ xdst,
                                  float* __restrict__ mh) {
    int w = (blockIdx.x * blockDim.x + threadIdx.x) >> 5;
    int lane = threadIdx.x & 31;
    if (w >= n_dst) return;
    int beg = off[w], end = off[w + 1];
    const float INF = __int_as_float(0x7f800000);
    float4 m0 = make_float4(INF, INF, INF, INF);
    float4 m1 = m0;
    for (int j = beg; j < end; j++) {
        int s = col[j];
        const float4* r = reinterpret_cast<const float4*>(xsrc + (size_t)s * H);
        float4 v0 = r[lane];
        float4 v1 = r[lane + 32];
        m0.x = fminf(m0.x, v0.x); m0.y = fminf(m0.y, v0.y);
        m0.z = fminf(m0.z, v0.z); m0.w = fminf(m0.w, v0.w);
        m1.x = fminf(m1.x, v1.x); m1.y = fminf(m1.y, v1.y);
        m1.z = fminf(m1.z, v1.z); m1.w = fminf(m1.w, v1.w);
    }
    const float4* xd = reinterpret_cast<const float4*>(xdst + (size_t)w * H);
    float4 d0 = xd[lane], d1 = xd[lane + 32];
    float4 o0, o1;
    if (beg < end) {
        o0 = make_float4(d0.x - m0.x, d0.y - m0.y, d0.z - m0.z, d0.w - m0.w);
        o1 = make_float4(d1.x - m1.x, d1.y - m1.y, d1.z - m1.z, d1.w - m1.w);
    } else {
        o0 = make_float4(0.f, 0.f, 0.f, 0.f);
        o1 = o0;
    }
    float4* mo = reinterpret_cast<float4*>(mh + (size_t)w * H);
    mo[lane] = o0;
    mo[lane + 32] = o1;
}

// ---------- tensor-core conv GEMM: out = x + leaky([x | mh] @ W + b) ----------
// block tile 128x128x32, 8 warps (2x4), warp tile 64x32, tf32 m16n8k8
#define BM 128
#define BN 128
#define BK 32
#define ASTR 36
#define BSTR 136

__global__ __launch_bounds__(256) void conv_gemm_tc(const float* __restrict__ x,
                                                    const float* __restrict__ mh,
                                                    const float* __restrict__ W,
                                                    const float* __restrict__ bias,
                                                    float* __restrict__ out, int M) {
    __shared__ unsigned As[BM * ASTR];
    __shared__ unsigned Bs[BK * BSTR];
    int tid = threadIdx.x;
    int warp = tid >> 5, lane = tid & 31;
    int g = lane >> 2, t = lane & 3;
    int wr = warp >> 2, wc = warp & 3;     // 2x4 warp grid
    int m_w = wr * 64, n_w = wc * 32;
    int bm = blockIdx.x * BM, bn = blockIdx.y * BN;

    float c[4][4][4];
#pragma unroll
    for (int i = 0; i < 4; i++)
#pragma unroll
        for (int j = 0; j < 4; j++)
#pragma unroll
            for (int q = 0; q < 4; q++) c[i][j][q] = 0.f;

    for (int k0 = 0; k0 < 512; k0 += BK) {
        const float* Ab = (k0 < 256) ? x : mh;
        int kk = k0 & 255;
        // A tile: 128x32 floats = 1024 float4, 4 per thread
#pragma unroll
        for (int r = 0; r < 4; r++) {
            int idx = tid + r * 256;
            int row = idx >> 3, c4 = (idx & 7) * 4;
            float4 v = make_float4(0.f, 0.f, 0.f, 0.f);
            if (bm + row < M)
                v = *reinterpret_cast<const float4*>(Ab + (size_t)(bm + row) * H + kk + c4);
            unsigned* p = &As[row * ASTR + c4];
            p[0] = f2tf32(v.x); p[1] = f2tf32(v.y);
            p[2] = f2tf32(v.z); p[3] = f2tf32(v.w);
        }
        // B tile: 32x128 floats = 1024 float4, 4 per thread
#pragma unroll
        for (int r = 0; r < 4; r++) {
            int idx = tid + r * 256;
            int row = idx >> 5, c4 = (idx & 31) * 4;
            float4 v = *reinterpret_cast<const float4*>(W + (size_t)(k0 + row) * H + bn + c4);
            unsigned* p = &Bs[row * BSTR + c4];
            p[0] = f2tf32(v.x); p[1] = f2tf32(v.y);
            p[2] = f2tf32(v.z); p[3] = f2tf32(v.w);
        }
        __syncthreads();
#pragma unroll
        for (int ks = 0; ks < 4; ks++) {
            int kb = ks * 8;
            unsigned a[4][4], b[4][2];
#pragma unroll
            for (int i = 0; i < 4; i++) {
                int mb = m_w + i * 16;
                a[i][0] = As[(mb + g) * ASTR + kb + t];
                a[i][1] = As[(mb + g + 8) * ASTR + kb + t];
                a[i][2] = As[(mb + g) * ASTR + kb + t + 4];
                a[i][3] = As[(mb + g + 8) * ASTR + kb + t + 4];
            }
#pragma unroll
            for (int j = 0; j < 4; j++) {
                int nb = n_w + j * 8;
                b[j][0] = Bs[(kb + t) * BSTR + nb + g];
                b[j][1] = Bs[(kb + t + 4) * BSTR + nb + g];
            }
#pragma unroll
            for (int i = 0; i < 4; i++)
#pragma unroll
                for (int j = 0; j < 4; j++) mma_tf32(c[i][j], a[i], b[j]);
        }
        __syncthreads();
    }

    // epilogue: out = x + leaky(c + bias)
#pragma unroll
    for (int i = 0; i < 4; i++) {
        int r0 = bm + m_w + i * 16 + g;
        int r1 = r0 + 8;
#pragma unroll
        for (int j = 0; j < 4; j++) {
            int col = bn + n_w + j * 8 + t * 2;
            float b0 = bias[col], b1 = bias[col + 1];
            if (r0 < M) {
                size_t o = (size_t)r0 * H + col;
                out[o]     = x[o]     + leaky(c[i][j][0] + b0);
                out[o + 1] = x[o + 1] + leaky(c[i][j][1] + b1);
            }
            if (r1 < M) {
                size_t o = (size_t)r1 * H + col;
                out[o]     = x[o]     + leaky(c[i][j][2] + b0);
                out[o + 1] = x[o + 1] + leaky(c[i][j][3] + b1);
            }
        }
    }
}

// ---------- launch ----------
static inline int cdiv(int a, int b) { return (a + b - 1) / b; }

static void run_conv(const int* idx, int n_pairs, int n_dst,
                     const float* xsrc, const float* xdst,
                     const float* W, const float* bias, float* outbuf,
                     float* pmh, int* pcnt, int* poff, int* pcur, int* pcol) {
    const int* dst = idx;
    const int* src = idx + n_pairs;
    cudaMemsetAsync(pcnt, 0, (size_t)(n_dst + 1) * sizeof(int));
    count_kernel<<<cdiv(n_pairs, 256), 256>>>(dst, n_pairs, pcnt);
    scan_kernel<<<1, 1024>>>(pcnt, n_dst, poff, pcur);
    fill_kernel<<<cdiv(n_pairs, 256), 256>>>(dst, src, n_pairs, pcur, pcol);
    segmin_csr_kernel<<<cdiv(n_dst * 32, 256), 256>>>(poff, pcol, n_dst, xsrc, xdst, pmh);
    dim3 grid(cdiv(n_dst, BM), 2);
    conv_gemm_tc<<<grid, 256>>>(xdst, pmh, W, bias, outbuf, n_dst);
}

extern "C" void kernel_launch(void* const* d_in, const int* in_sizes, int n_in,
                              void* d_out, int out_size) {
    const float* vp  = (const float*)d_in[0];
    const float* ec  = (const float*)d_in[1];
    const float* ecp = (const float*)d_in[2];
    const float* ecf = (const float*)d_in[3];
    const float* lt  = (const float*)d_in[4];
    const float* fs  = (const float*)d_in[5];
    const float* fsp = (const float*)d_in[6];
    const float* fsf = (const float*)d_in[7];
    const int* ev = (const int*)d_in[8];
    const int* le = (const int*)d_in[9];
    const int* fl = (const int*)d_in[10];
    const float* Wv = (const float*)d_in[11]; const float* bv = (const float*)d_in[12];
    const float* We = (const float*)d_in[13]; const float* be = (const float*)d_in[14];
    const float* Wl = (const float*)d_in[15]; const float* bl = (const float*)d_in[16];
    const float* Wf = (const float*)d_in[17]; const float* bf = (const float*)d_in[18];
    const float* Wve = (const float*)d_in[19]; const float* bve = (const float*)d_in[20];
    const float* Wel = (const float*)d_in[21]; const float* bel = (const float*)d_in[22];
    const float* Wlf = (const float*)d_in[23]; const float* blf = (const float*)d_in[24];

    int NVn = in_sizes[0] / 3;
    int NEn = in_sizes[1] / 8;
    int NLn = in_sizes[4] / 10;
    int NFn = in_sizes[5] / 12;
    int nEV = in_sizes[8] / 2;
    int nLE = in_sizes[9] / 2;
    int nFL = in_sizes[10] / 2;

    float *pv, *pe, *peo, *pl, *pf, *pmh;
    int *pcnt, *poff, *pcur, *pcol;
    cudaGetSymbolAddress((void**)&pv,   g_v);
    cudaGetSymbolAddress((void**)&pe,   g_e);
    cudaGetSymbolAddress((void**)&peo,  g_eo);
    cudaGetSymbolAddress((void**)&pl,   g_l);
    cudaGetSymbolAddress((void**)&pf,   g_f);
    cudaGetSymbolAddress((void**)&pmh,  g_mh);
    cudaGetSymbolAddress((void**)&pcnt, g_cnt);
    cudaGetSymbolAddress((void**)&poff, g_off);
    cudaGetSymbolAddress((void**)&pcur, g_cur);
    cudaGetSymbolAddress((void**)&pcol, g_col);

    // embeddings
    embed_kernel<<<cdiv(NVn, 8), 256>>>(vp, 3, nullptr, 0, nullptr, 0, Wv, bv, pv, NVn);
    embed_kernel<<<cdiv(NEn, 8), 256>>>(ec, 8, ecp, 6, ecf, 1, We, be, pe, NEn);
    embed_kernel<<<cdiv(NLn, 8), 256>>>(lt, 10, nullptr, 0, nullptr, 0, Wl, bl, pl, NLn);
    embed_kernel<<<cdiv(NFn, 8), 256>>>(fs, 12, fsp, 4, fsf, 1, Wf, bf, pf, NFn);

    // conv 1: vertices -> edges
    run_conv(ev, nEV, NEn, pv, pe, Wve, bve, peo, pmh, pcnt, poff, pcur, pcol);
    // conv 2: edges -> loops (output reuses g_v)
    run_conv(le, nLE, NLn, peo, pl, Wel, bel, pv, pmh, pcnt, poff, pcur, pcol);
    // conv 3: loops -> faces (output = d_out)
    run_conv(fl, nFL, NFn, pv, pf, Wlf, blf, (float*)d_out, pmh, pcnt, poff, pcur, pcol);
}

// round 4
// speedup vs baseline: 3.0390x; 1.5066x over previous
#include <cuda_runtime.h>
#include <cstdint>

#define H 256

#define MAXV 100000
#define MAXE 150000
#define MAXL 80000
#define MAXF 60000
#define MAXPAIR 320000

// scratch
__device__ float    g_v[(size_t)MAXV * H];
__device__ float    g_e[(size_t)MAXE * H];
__device__ float    g_eo[(size_t)MAXE * H];
__device__ float    g_l[(size_t)MAXL * H];
__device__ float    g_f[(size_t)MAXF * H];
__device__ float    g_mh[(size_t)MAXE * H];
__device__ int      g_cnt[MAXE + 1];
__device__ int      g_off[MAXE + 1];
__device__ int      g_cur[MAXE + 1];
__device__ int      g_col[MAXPAIR];
__device__ int      g_bsum[64];

// ---------- helpers ----------
__device__ __forceinline__ float leaky(float a) { return a >= 0.f ? a : 0.01f * a; }

__device__ __forceinline__ void mma_tf32(float c[4], const unsigned a[4], const unsigned b[2]) {
    asm volatile(
        "mma.sync.aligned.m16n8k8.row.col.f32.tf32.tf32.f32 "
        "{%0,%1,%2,%3},{%4,%5,%6,%7},{%8,%9},{%0,%1,%2,%3};"
        : "+f"(c[0]), "+f"(c[1]), "+f"(c[2]), "+f"(c[3])
        : "r"(a[0]), "r"(a[1]), "r"(a[2]), "r"(a[3]), "r"(b[0]), "r"(b[1]));
}

__device__ __forceinline__ void cp16(float* s, const float* g, bool valid) {
    unsigned saddr = (unsigned)__cvta_generic_to_shared(s);
    int sz = valid ? 16 : 0;
    asm volatile("cp.async.cg.shared.global [%0], [%1], 16, %2;" :: "r"(saddr), "l"(g), "r"(sz));
}
__device__ __forceinline__ void cp_commit() { asm volatile("cp.async.commit_group;"); }
template<int N> __device__ __forceinline__ void cp_wait() { asm volatile("cp.async.wait_group %0;" :: "n"(N)); }

// ---------- embedding: 16 rows/block, each thread: 4 rows x 4 cols ----------
__global__ void embed_kernel(const float* __restrict__ s0, int w0,
                             const float* __restrict__ s1, int w1,
                             const float* __restrict__ s2, int w2,
                             const float* __restrict__ W, const float* __restrict__ bias,
                             float* __restrict__ out, int n) {
    const int RB = 16;
    int row0 = blockIdx.x * RB;
    int tid = threadIdx.x;
    int cg = tid & 63, rg = tid >> 6;
    int IN = w0 + w1 + w2;
    __shared__ float xs[RB][21];

    for (int i = tid; i < RB * IN; i += 256) {
        int r = i / IN, k = i % IN;
        int row = row0 + r;
        float v = 0.f;
        if (row < n) {
            if (k < w0)            v = s0[(size_t)row * w0 + k];
            else if (k < w0 + w1)  v = s1[(size_t)row * w1 + (k - w0)];
            else                   v = s2[row];
        }
        xs[r][k] = v;
    }
    __syncthreads();

    float4 b = reinterpret_cast<const float4*>(bias)[cg];
    float4 acc[4];
#pragma unroll
    for (int q = 0; q < 4; q++) acc[q] = b;
    for (int k = 0; k < IN; k++) {
        float4 w = reinterpret_cast<const float4*>(W + (size_t)k * H)[cg];
#pragma unroll
        for (int q = 0; q < 4; q++) {
            float xv = xs[rg * 4 + q][k];
            acc[q].x += xv * w.x; acc[q].y += xv * w.y;
            acc[q].z += xv * w.z; acc[q].w += xv * w.w;
        }
    }
#pragma unroll
    for (int q = 0; q < 4; q++) {
        int row = row0 + rg * 4 + q;
        if (row < n) {
            float4 o = make_float4(leaky(acc[q].x), leaky(acc[q].y),
                                   leaky(acc[q].z), leaky(acc[q].w));
            reinterpret_cast<float4*>(out + (size_t)row * H)[cg] = o;
        }
    }
}

// ---------- CSR build ----------
__global__ void count_kernel(const int* __restrict__ dst, int n_pairs, int* __restrict__ cnt) {
    int i = blockIdx.x * blockDim.x + threadIdx.x;
    if (i < n_pairs) atomicAdd(&cnt[dst[i]], 1);
}

// phase1: per-block (4096 elems) local exclusive scan + block sums
__global__ void scan_phase1(const int* __restrict__ cnt, int n,
                            int* __restrict__ off, int* __restrict__ bsum) {
    __shared__ int wsum[32];
    int tid = threadIdx.x, lane = tid & 31, wid = tid >> 5;
    int base = blockIdx.x * 4096 + tid * 4;
    int v0 = (base     < n) ? cnt[base]     : 0;
    int v1 = (base + 1 < n) ? cnt[base + 1] : 0;
    int v2 = (base + 2 < n) ? cnt[base + 2] : 0;
    int v3 = (base + 3 < n) ? cnt[base + 3] : 0;
    int s = v0 + v1 + v2 + v3;
    int x = s;
#pragma unroll
    for (int d = 1; d < 32; d <<= 1) {
        int y = __shfl_up_sync(~0u, x, d);
        if (lane >= d) x += y;
    }
    if (lane == 31) wsum[wid] = x;
    __syncthreads();
    if (wid == 0) {
        int w = wsum[lane];
#pragma unroll
        for (int d = 1; d < 32; d <<= 1) {
            int y = __shfl_up_sync(~0u, w, d);
            if (lane >= d) w += y;
        }
        wsum[lane] = w;
    }
    __syncthreads();
    int run = x - s + (wid ? wsum[wid - 1] : 0);
    if (base     < n) off[base]     = run; run += v0;
    if (base + 1 < n) off[base + 1] = run; run += v1;
    if (base + 2 < n) off[base + 2] = run; run += v2;
    if (base + 3 < n) off[base + 3] = run;
    if (tid == 0) bsum[blockIdx.x] = wsum[31];
}

// phase2: scan block sums (<=64), write total to off[n]
__global__ void scan_phase2(int* __restrict__ bsum, int nb, int* __restrict__ off, int n) {
    __shared__ int tmp[64];
    int tid = threadIdx.x;
    int v = (tid < nb) ? bsum[tid] : 0;
    tmp[tid] = v;
    __syncthreads();
    int x = v;
    for (int d = 1; d < 64; d <<= 1) {
        int y = (tid >= d) ? tmp[tid - d] : 0;
        __syncthreads();
        x += y;
        tmp[tid] = x;
        __syncthreads();
    }
    if (tid < nb) bsum[tid] = x - v;
    if (tid == 63) off[n] = x;
}

// phase3: add block offsets, copy to cur
__global__ void scan_phase3(int* __restrict__ off, const int* __restrict__ bsum,
                            int n, int* __restrict__ cur) {
    int i = blockIdx.x * blockDim.x + threadIdx.x;
    if (i < n) {
        int o = off[i] + bsum[i >> 12];
        off[i] = o;
        cur[i] = o;
    }
}

__global__ void fill_kernel(const int* __restrict__ dst, const int* __restrict__ src,
                            int n_pairs, int* __restrict__ cur, int* __restrict__ col) {
    int i = blockIdx.x * blockDim.x + threadIdx.x;
    if (i < n_pairs) {
        int pos = atomicAdd(&cur[dst[i]], 1);
        col[pos] = src[i];
    }
}

// ---------- fused segment-min + (x_dst - min) ----------
__global__ void segmin_csr_kernel(const int* __restrict__ off, const int* __restrict__ col,
                                  int n_dst,
                                  const float* __restrict__ xsrc,
                                  const float* __restrict__ xdst,
                                  float* __restrict__ mh) {
    int w = (blockIdx.x * blockDim.x + threadIdx.x) >> 5;
    int lane = threadIdx.x & 31;
    if (w >= n_dst) return;
    int beg = off[w], end = off[w + 1];
    const float INF = __int_as_float(0x7f800000);
    float4 m0 = make_float4(INF, INF, INF, INF);
    float4 m1 = m0;
    for (int j = beg; j < end; j++) {
        int s = col[j];
        const float4* r = reinterpret_cast<const float4*>(xsrc + (size_t)s * H);
        float4 v0 = r[lane];
        float4 v1 = r[lane + 32];
        m0.x = fminf(m0.x, v0.x); m0.y = fminf(m0.y, v0.y);
        m0.z = fminf(m0.z, v0.z); m0.w = fminf(m0.w, v0.w);
        m1.x = fminf(m1.x, v1.x); m1.y = fminf(m1.y, v1.y);
        m1.z = fminf(m1.z, v1.z); m1.w = fminf(m1.w, v1.w);
    }
    const float4* xd = reinterpret_cast<const float4*>(xdst + (size_t)w * H);
    float4 d0 = xd[lane], d1 = xd[lane + 32];
    float4 o0, o1;
    if (beg < end) {
        o0 = make_float4(d0.x - m0.x, d0.y - m0.y, d0.z - m0.z, d0.w - m0.w);
        o1 = make_float4(d1.x - m1.x, d1.y - m1.y, d1.z - m1.z, d1.w - m1.w);
    } else {
        o0 = make_float4(0.f, 0.f, 0.f, 0.f);
        o1 = o0;
    }
    float4* mo = reinterpret_cast<float4*>(mh + (size_t)w * H);
    mo[lane] = o0;
    mo[lane + 32] = o1;
}

// ---------- tensor-core conv GEMM with double-buffered cp.async ----------
#define BM 128
#define BN 128
#define BK 32
#define ASTR 36
#define BSTR 136
#define ASZ (BM * ASTR)
#define BSZ (BK * BSTR)
#define SMEM_BYTES ((ASZ + BSZ) * 2 * 4)

__global__ __launch_bounds__(256) void conv_gemm_tc(const float* __restrict__ x,
                                                    const float* __restrict__ mh,
                                                    const float* __restrict__ W,
                                                    const float* __restrict__ bias,
                                                    float* __restrict__ out, int M) {
    extern __shared__ float sm[];
    float* Asm = sm;                    // 2 x ASZ
    float* Bsm = sm + 2 * ASZ;          // 2 x BSZ
    int tid = threadIdx.x;
    int warp = tid >> 5, lane = tid & 31;
    int g = lane >> 2, t = lane & 3;
    int wr = warp >> 2, wc = warp & 3;
    int m_w = wr * 64, n_w = wc * 32;
    int bm = blockIdx.x * BM, bn = blockIdx.y * BN;

    // prefetch thread roles (fixed per thread)
    int arow = tid >> 3, ac4 = (tid & 7) * 4;       // 4 stages of +32 rows? no: 4 chunks via +256
    int brow = tid >> 5, bc4 = (tid & 31) * 4;

    float c[4][4][4];
#pragma unroll
    for (int i = 0; i < 4; i++)
#pragma unroll
        for (int j = 0; j < 4; j++)
#pragma unroll
            for (int q = 0; q < 4; q++) c[i][j][q] = 0.f;

    auto prefetch = [&](int k0, int buf) {
        const float* Ab = (k0 < 256) ? x : mh;
        int kk = k0 & 255;
        float* Ad = Asm + buf * ASZ;
        float* Bd = Bsm + buf * BSZ;
#pragma unroll
        for (int r = 0; r < 4; r++) {
            int row = arow + r * 32;
            bool v = (bm + row) < M;
            const float* gp = Ab + (size_t)(v ? bm + row : 0) * H + kk + ac4;
            cp16(Ad + row * ASTR + ac4, gp, v);
        }
#pragma unroll
        for (int r = 0; r < 4; r++) {
            int row = brow + r * 8;
            cp16(Bd + row * BSTR + bc4, W + (size_t)(k0 + row) * H + bn + bc4, true);
        }
        cp_commit();
    };

    prefetch(0, 0);

    for (int it = 0; it < 16; it++) {
        int buf = it & 1;
        if (it < 15) {
            prefetch((it + 1) * BK, buf ^ 1);
            cp_wait<1>();
        } else {
            cp_wait<0>();
        }
        __syncthreads();

        const float* Asb = Asm + buf * ASZ;
        const float* Bsb = Bsm + buf * BSZ;
#pragma unroll
        for (int ks = 0; ks < 4; ks++) {
            int kb = ks * 8;
            unsigned a[4][4], b[4][2];
#pragma unroll
            for (int i = 0; i < 4; i++) {
                int mb = m_w + i * 16;
                a[i][0] = __float_as_uint(Asb[(mb + g) * ASTR + kb + t]);
                a[i][1] = __float_as_uint(Asb[(mb + g + 8) * ASTR + kb + t]);
                a[i][2] = __float_as_uint(Asb[(mb + g) * ASTR + kb + t + 4]);
                a[i][3] = __float_as_uint(Asb[(mb + g + 8) * ASTR + kb + t + 4]);
            }
#pragma unroll
            for (int j = 0; j < 4; j++) {
                int nb = n_w + j * 8;
                b[j][0] = __float_as_uint(Bsb[(kb + t) * BSTR + nb + g]);
                b[j][1] = __float_as_uint(Bsb[(kb + t + 4) * BSTR + nb + g]);
            }
#pragma unroll
            for (int i = 0; i < 4; i++)
#pragma unroll
                for (int j = 0; j < 4; j++) mma_tf32(c[i][j], a[i], b[j]);
        }
        __syncthreads();
    }

    // epilogue: out = x + leaky(c + bias)
#pragma unroll
    for (int i = 0; i < 4; i++) {
        int r0 = bm + m_w + i * 16 + g;
        int r1 = r0 + 8;
#pragma unroll
        for (int j = 0; j < 4; j++) {
            int col = bn + n_w + j * 8 + t * 2;
            float b0 = bias[col], b1 = bias[col + 1];
            if (r0 < M) {
                size_t o = (size_t)r0 * H + col;
                out[o]     = x[o]     + leaky(c[i][j][0] + b0);
                out[o + 1] = x[o + 1] + leaky(c[i][j][1] + b1);
            }
            if (r1 < M) {
                size_t o = (size_t)r1 * H + col;
                out[o]     = x[o]     + leaky(c[i][j][2] + b0);
                out[o + 1] = x[o + 1] + leaky(c[i][j][3] + b1);
            }
        }
    }
}

// ---------- launch ----------
static inline int cdiv(int a, int b) { return (a + b - 1) / b; }

static void run_conv(const int* idx, int n_pairs, int n_dst,
                     const float* xsrc, const float* xdst,
                     const float* W, const float* bias, float* outbuf,
                     float* pmh, int* pcnt, int* poff, int* pcur, int* pcol, int* pbsum) {
    const int* dst = idx;
    const int* src = idx + n_pairs;
    cudaMemsetAsync(pcnt, 0, (size_t)n_dst * sizeof(int));
    count_kernel<<<cdiv(n_pairs, 256), 256>>>(dst, n_pairs, pcnt);
    int nb = cdiv(n_dst, 4096);
    scan_phase1<<<nb, 1024>>>(pcnt, n_dst, poff, pbsum);
    scan_phase2<<<1, 64>>>(pbsum, nb, poff, n_dst);
    scan_phase3<<<cdiv(n_dst, 256), 256>>>(poff, pbsum, n_dst, pcur);
    fill_kernel<<<cdiv(n_pairs, 256), 256>>>(dst, src, n_pairs, pcur, pcol);
    segmin_csr_kernel<<<cdiv(n_dst * 32, 256), 256>>>(poff, pcol, n_dst, xsrc, xdst, pmh);
    dim3 grid(cdiv(n_dst, BM), 2);
    conv_gemm_tc<<<grid, 256, SMEM_BYTES>>>(xdst, pmh, W, bias, outbuf, n_dst);
}

extern "C" void kernel_launch(void* const* d_in, const int* in_sizes, int n_in,
                              void* d_out, int out_size) {
    const float* vp  = (const float*)d_in[0];
    const float* ec  = (const float*)d_in[1];
    const float* ecp = (const float*)d_in[2];
    const float* ecf = (const float*)d_in[3];
    const float* lt  = (const float*)d_in[4];
    const float* fs  = (const float*)d_in[5];
    const float* fsp = (const float*)d_in[6];
    const float* fsf = (const float*)d_in[7];
    const int* ev = (const int*)d_in[8];
    const int* le = (const int*)d_in[9];
    const int* fl = (const int*)d_in[10];
    const float* Wv = (const float*)d_in[11]; const float* bv = (const float*)d_in[12];
    const float* We = (const float*)d_in[13]; const float* be = (const float*)d_in[14];
    const float* Wl = (const float*)d_in[15]; const float* bl = (const float*)d_in[16];
    const float* Wf = (const float*)d_in[17]; const float* bf = (const float*)d_in[18];
    const float* Wve = (const float*)d_in[19]; const float* bve = (const float*)d_in[20];
    const float* Wel = (const float*)d_in[21]; const float* bel = (const float*)d_in[22];
    const float* Wlf = (const float*)d_in[23]; const float* blf = (const float*)d_in[24];

    int NVn = in_sizes[0] / 3;
    int NEn = in_sizes[1] / 8;
    int NLn = in_sizes[4] / 10;
    int NFn = in_sizes[5] / 12;
    int nEV = in_sizes[8] / 2;
    int nLE = in_sizes[9] / 2;
    int nFL = in_sizes[10] / 2;

    float *pv, *pe, *peo, *pl, *pf, *pmh;
    int *pcnt, *poff, *pcur, *pcol, *pbsum;
    cudaGetSymbolAddress((void**)&pv,    g_v);
    cudaGetSymbolAddress((void**)&pe,    g_e);
    cudaGetSymbolAddress((void**)&peo,   g_eo);
    cudaGetSymbolAddress((void**)&pl,    g_l);
    cudaGetSymbolAddress((void**)&pf,    g_f);
    cudaGetSymbolAddress((void**)&pmh,   g_mh);
    cudaGetSymbolAddress((void**)&pcnt,  g_cnt);
    cudaGetSymbolAddress((void**)&poff,  g_off);
    cudaGetSymbolAddress((void**)&pcur,  g_cur);
    cudaGetSymbolAddress((void**)&pcol,  g_col);
    cudaGetSymbolAddress((void**)&pbsum, g_bsum);

    cudaFuncSetAttribute(conv_gemm_tc, cudaFuncAttributeMaxDynamicSharedMemorySize, SMEM_BYTES);

    // embeddings
    embed_kernel<<<cdiv(NVn, 16), 256>>>(vp, 3, nullptr, 0, nullptr, 0, Wv, bv, pv, NVn);
    embed_kernel<<<cdiv(NEn, 16), 256>>>(ec, 8, ecp, 6, ecf, 1, We, be, pe, NEn);
    embed_kernel<<<cdiv(NLn, 16), 256>>>(lt, 10, nullptr, 0, nullptr, 0, Wl, bl, pl, NLn);
    embed_kernel<<<cdiv(NFn, 16), 256>>>(fs, 12, fsp, 4, fsf, 1, Wf, bf, pf, NFn);

    // conv 1: vertices -> edges
    run_conv(ev, nEV, NEn, pv, pe, Wve, bve, peo, pmh, pcnt, poff, pcur, pcol, pbsum);
    // conv 2: edges -> loops (output reuses g_v)
    run_conv(le, nLE, NLn, peo, pl, Wel, bel, pv, pmh, pcnt, poff, pcur, pcol, pbsum);
    // conv 3: loops -> faces (output = d_out)
    run_conv(fl, nFL, NFn, pv, pf, Wlf, blf, (float*)d_out, pmh, pcnt, poff, pcur, pcol, pbsum);
}